// round 2
// baseline (speedup 1.0000x reference)
#include <cuda_runtime.h>
#include <cuda_bf16.h>
#include <math.h>

// Problem constants
#define BB   16
#define LQ   1024
#define DD   256
#define HH   8
#define LL   4
#define PP   4
#define DFF  1024
#define LV   5440
#define DH   32
#define NTOK (BB*LQ)        // 16384
#define NV   (BB*LV)        // 87040

// ---------------- scratch (device globals; no allocs allowed) ----------------
__device__ float g_qk  [(size_t)NTOK*512];
__device__ float g_v   [(size_t)NTOK*256];
__device__ float g_att [(size_t)NTOK*256];
__device__ float g_att2[(size_t)NTOK*256];
__device__ float g_t1  [(size_t)NTOK*256];
__device__ float g_value[(size_t)NV*256];
__device__ float g_off [(size_t)NTOK*256];
__device__ float g_attw[(size_t)NTOK*128];
__device__ float g_samp[(size_t)NTOK*256];
__device__ float g_ms  [(size_t)NTOK*256];
__device__ float g_t2  [(size_t)NTOK*256];
__device__ float g_ffn1[(size_t)NTOK*1024];
__device__ float g_ffn2[(size_t)NTOK*256];

// ---------------- generic GEMM: C[N,M] = (A0 (+A1)) @ W[M,K]^T + bias --------
// BM=BN=64, BK=16, 256 threads, 4x4 microtile. All dims: N%64==0, M%64==0, K%16==0.
__global__ void __launch_bounds__(256) gemm_kernel(
    const float* __restrict__ A0, const float* __restrict__ A1,
    const float* __restrict__ W,  const float* __restrict__ bias,
    float* __restrict__ C, int N, int K, int M, int relu)
{
    __shared__ float As[16][68];
    __shared__ float Bs[16][68];
    const int tid = threadIdx.x;
    const int r0 = blockIdx.y * 64;
    const int c0 = blockIdx.x * 64;
    const int lm = tid >> 2;          // 0..63
    const int lk = (tid & 3) * 4;     // 0,4,8,12
    const int ty = tid >> 4;          // 0..15
    const int tx = tid & 15;          // 0..15

    float acc[4][4];
    #pragma unroll
    for (int i = 0; i < 4; i++)
        #pragma unroll
        for (int j = 0; j < 4; j++) acc[i][j] = 0.f;

    const float* Aptr  = A0 + (size_t)(r0 + lm) * K + lk;
    const float* A1ptr = A1 ? (A1 + (size_t)(r0 + lm) * K + lk) : nullptr;
    const float* Wptr  = W  + (size_t)(c0 + lm) * K + lk;

    for (int kt = 0; kt < K; kt += 16) {
        float4 av = *(const float4*)(Aptr + kt);
        if (A1ptr) {
            float4 t = *(const float4*)(A1ptr + kt);
            av.x += t.x; av.y += t.y; av.z += t.z; av.w += t.w;
        }
        float4 bv = *(const float4*)(Wptr + kt);
        __syncthreads();
        As[lk+0][lm] = av.x; As[lk+1][lm] = av.y; As[lk+2][lm] = av.z; As[lk+3][lm] = av.w;
        Bs[lk+0][lm] = bv.x; Bs[lk+1][lm] = bv.y; Bs[lk+2][lm] = bv.z; Bs[lk+3][lm] = bv.w;
        __syncthreads();
        #pragma unroll
        for (int k = 0; k < 16; k++) {
            float4 a = *(const float4*)&As[k][ty*4];
            float4 b = *(const float4*)&Bs[k][tx*4];
            float ar[4] = {a.x, a.y, a.z, a.w};
            float br[4] = {b.x, b.y, b.z, b.w};
            #pragma unroll
            for (int i = 0; i < 4; i++)
                #pragma unroll
                for (int j = 0; j < 4; j++)
                    acc[i][j] = fmaf(ar[i], br[j], acc[i][j]);
        }
    }
    #pragma unroll
    for (int i = 0; i < 4; i++) {
        const int row = r0 + ty*4 + i;
        #pragma unroll
        for (int j = 0; j < 4; j++) {
            const int col = c0 + tx*4 + j;
            float v = acc[i][j] + bias[col];
            if (relu) v = fmaxf(v, 0.f);
            C[(size_t)row * M + col] = v;
        }
    }
}

// ---------------- flash attention: one query per thread -----------------------
// QK: [NTOK,512] (q | k), V: [NTOK,256]. grid (LQ/128, B*H), 128 threads.
__global__ void __launch_bounds__(128) attn_kernel(
    const float* __restrict__ QK, const float* __restrict__ V, float* __restrict__ O)
{
    const int bh = blockIdx.y;
    const int b = bh >> 3, h = bh & 7;
    const int tid = threadIdx.x;
    const int qi = blockIdx.x * 128 + tid;

    float q[32];
    {
        const size_t qrow = ((size_t)b * LQ + qi) * 512 + h * 32;
        #pragma unroll
        for (int d4 = 0; d4 < 8; d4++) {
            float4 t = *(const float4*)(QK + qrow + d4 * 4);
            q[d4*4+0] = t.x; q[d4*4+1] = t.y; q[d4*4+2] = t.z; q[d4*4+3] = t.w;
        }
    }
    __shared__ float Ks[32][32];
    __shared__ float Vs[32][32];

    float o[32];
    #pragma unroll
    for (int d = 0; d < 32; d++) o[d] = 0.f;
    float m = -1e30f, lsum = 0.f;
    const float scale = 0.17677669529663687f;   // 1/sqrt(32)

    const size_t kbase = ((size_t)b * LQ) * 512 + 256 + h * 32;
    const size_t vbase = ((size_t)b * LQ) * 256 + h * 32;

    for (int kt = 0; kt < LQ; kt += 32) {
        __syncthreads();
        #pragma unroll
        for (int i = 0; i < 2; i++) {
            const int f4  = tid * 2 + i;       // 0..255
            const int key = f4 >> 3;
            const int d4  = (f4 & 7) * 4;
            *(float4*)&Ks[key][d4] = *(const float4*)(QK + kbase + (size_t)(kt + key) * 512 + d4);
            *(float4*)&Vs[key][d4] = *(const float4*)(V  + vbase + (size_t)(kt + key) * 256 + d4);
        }
        __syncthreads();

        float s[32];
        #pragma unroll
        for (int key = 0; key < 32; key++) {
            const float4* K4 = (const float4*)Ks[key];
            float acc = 0.f;
            #pragma unroll
            for (int d4 = 0; d4 < 8; d4++) {
                float4 kv = K4[d4];
                acc = fmaf(q[d4*4+0], kv.x, acc);
                acc = fmaf(q[d4*4+1], kv.y, acc);
                acc = fmaf(q[d4*4+2], kv.z, acc);
                acc = fmaf(q[d4*4+3], kv.w, acc);
            }
            s[key] = acc * scale;
        }
        float tmax = s[0];
        #pragma unroll
        for (int key = 1; key < 32; key++) tmax = fmaxf(tmax, s[key]);
        const float mn = fmaxf(m, tmax);
        const float corr = __expf(m - mn);
        lsum *= corr;
        #pragma unroll
        for (int d = 0; d < 32; d++) o[d] *= corr;
        #pragma unroll
        for (int key = 0; key < 32; key++) {
            const float p = __expf(s[key] - mn);
            lsum += p;
            const float4* V4 = (const float4*)Vs[key];
            #pragma unroll
            for (int d4 = 0; d4 < 8; d4++) {
                float4 vv = V4[d4];
                o[d4*4+0] = fmaf(p, vv.x, o[d4*4+0]);
                o[d4*4+1] = fmaf(p, vv.y, o[d4*4+1]);
                o[d4*4+2] = fmaf(p, vv.z, o[d4*4+2]);
                o[d4*4+3] = fmaf(p, vv.w, o[d4*4+3]);
            }
        }
        m = mn;
    }
    const float inv = 1.f / lsum;
    const size_t orow = ((size_t)b * LQ + qi) * 256 + h * 32;
    #pragma unroll
    for (int d4 = 0; d4 < 8; d4++) {
        float4 t;
        t.x = o[d4*4+0]*inv; t.y = o[d4*4+1]*inv;
        t.z = o[d4*4+2]*inv; t.w = o[d4*4+3]*inv;
        *(float4*)(O + orow + d4*4) = t;
    }
}

// ---------------- residual + layernorm: Y = LN(A + Bres) ---------------------
// one warp per 256-col row; grid = rows/8, 256 threads.
__global__ void __launch_bounds__(256) ln_kernel(
    const float* __restrict__ A, const float* __restrict__ Bres,
    const float* __restrict__ g, const float* __restrict__ beta,
    float* __restrict__ Y)
{
    const int warp = threadIdx.x >> 5, lane = threadIdx.x & 31;
    const size_t row = (size_t)blockIdx.x * 8 + warp;
    const float* a = A    + row * 256;
    const float* b = Bres + row * 256;
    float v[8];
    #pragma unroll
    for (int i = 0; i < 2; i++) {
        float4 x = *(const float4*)(a + i*128 + lane*4);
        float4 y = *(const float4*)(b + i*128 + lane*4);
        v[i*4+0] = x.x + y.x; v[i*4+1] = x.y + y.y;
        v[i*4+2] = x.z + y.z; v[i*4+3] = x.w + y.w;
    }
    float sum = 0.f, sq = 0.f;
    #pragma unroll
    for (int i = 0; i < 8; i++) { sum += v[i]; sq = fmaf(v[i], v[i], sq); }
    #pragma unroll
    for (int off = 16; off > 0; off >>= 1) {
        sum += __shfl_xor_sync(0xffffffffu, sum, off);
        sq  += __shfl_xor_sync(0xffffffffu, sq,  off);
    }
    const float mean = sum * (1.f/256.f);
    const float var  = sq * (1.f/256.f) - mean * mean;
    const float inv  = rsqrtf(var + 1e-5f);
    #pragma unroll
    for (int i = 0; i < 2; i++) {
        const int col = i*128 + lane*4;
        float4 gg = *(const float4*)(g + col);
        float4 bb = *(const float4*)(beta + col);
        float4 out;
        out.x = (v[i*4+0]-mean)*inv*gg.x + bb.x;
        out.y = (v[i*4+1]-mean)*inv*gg.y + bb.y;
        out.z = (v[i*4+2]-mean)*inv*gg.z + bb.z;
        out.w = (v[i*4+3]-mean)*inv*gg.w + bb.w;
        *(float4*)(Y + row*256 + col) = out;
    }
}

// ---------------- softmax over 16 contiguous values per (token,h) ------------
__global__ void __launch_bounds__(256) softmax16_kernel(float* __restrict__ W)
{
    const int tid = blockIdx.x * 256 + threadIdx.x;
    if (tid >= NTOK * HH) return;
    float* p = W + (size_t)tid * 16;
    float v[16];
    #pragma unroll
    for (int i = 0; i < 4; i++) {
        float4 t = *(const float4*)(p + i*4);
        v[i*4+0]=t.x; v[i*4+1]=t.y; v[i*4+2]=t.z; v[i*4+3]=t.w;
    }
    float mx = v[0];
    #pragma unroll
    for (int i = 1; i < 16; i++) mx = fmaxf(mx, v[i]);
    float s = 0.f;
    #pragma unroll
    for (int i = 0; i < 16; i++) { v[i] = __expf(v[i]-mx); s += v[i]; }
    const float inv = 1.f / s;
    #pragma unroll
    for (int i = 0; i < 4; i++) {
        float4 t;
        t.x=v[i*4+0]*inv; t.y=v[i*4+1]*inv; t.z=v[i*4+2]*inv; t.w=v[i*4+3]*inv;
        *(float4*)(p + i*4) = t;
    }
}

// ---------------- deformable bilinear sampling -------------------------------
__device__ __forceinline__ float fetch_v(const float* __restrict__ value, size_t vb,
                                         int start, int WL2, int HL2, int xi, int yi)
{
    const bool ok = ((unsigned)xi < (unsigned)WL2) & ((unsigned)yi < (unsigned)HL2);
    const int xc = min(max(xi, 0), WL2 - 1);
    const int yc = min(max(yi, 0), HL2 - 1);
    const float val = value[vb + (size_t)(start + yc * WL2 + xc) * 256];
    return ok ? val : 0.f;
}

// one warp per (b,q,h); lane = channel. grid = NTOK*H/8 blocks of 256 threads.
__global__ void __launch_bounds__(256) sample_kernel(
    const float* __restrict__ ref, const float* __restrict__ off,
    const float* __restrict__ attw, const float* __restrict__ value,
    float* __restrict__ out)
{
    const int wg   = blockIdx.x * 8 + (threadIdx.x >> 5);
    const int lane = threadIdx.x & 31;
    const int h  = wg & 7;
    const int tq = wg >> 3;            // b*LQ + q
    const int b  = tq >> 10;

    const float* refp = ref  + (size_t)tq * (LL*2);
    const float* offp = off  + (size_t)tq * 256 + h * 32;   // (l*4+p)*2 within
    const float* awp  = attw + (size_t)tq * 128 + h * 16;
    const size_t vb   = ((size_t)b * LV) * 256 + h * 32 + lane;

    const int wls[4]    = {64, 32, 16, 8};
    const int hls[4]    = {64, 32, 16, 8};
    const int starts[4] = {0, 4096, 5120, 5376};

    float acc = 0.f;
    #pragma unroll
    for (int l = 0; l < 4; l++) {
        const int WL2 = wls[l], HL2 = hls[l], st = starts[l];
        const float rx = refp[l*2], ry = refp[l*2+1];
        #pragma unroll
        for (int p = 0; p < 4; p++) {
            const float ox = offp[(l*4+p)*2];
            const float oy = offp[(l*4+p)*2+1];
            const float aw = awp[l*4+p];
            const float x = fmaf(rx, (float)WL2, ox) - 0.5f;
            const float y = fmaf(ry, (float)HL2, oy) - 0.5f;
            const float xf = floorf(x), yf = floorf(y);
            const float lx = x - xf, ly = y - yf;
            const int x0 = (int)xf, y0 = (int)yf;
            const float v00 = fetch_v(value, vb, st, WL2, HL2, x0,   y0);
            const float v01 = fetch_v(value, vb, st, WL2, HL2, x0+1, y0);
            const float v10 = fetch_v(value, vb, st, WL2, HL2, x0,   y0+1);
            const float v11 = fetch_v(value, vb, st, WL2, HL2, x0+1, y0+1);
            const float top = v00 + lx * (v01 - v00);
            const float bot = v10 + lx * (v11 - v10);
            acc = fmaf(aw, top + ly * (bot - top), acc);
        }
    }
    out[(size_t)tq * 256 + h * 32 + lane] = acc;
}

// ---------------- host orchestration -----------------------------------------
extern "C" void kernel_launch(void* const* d_in, const int* in_sizes, int n_in,
                              void* d_out, int out_size)
{
    const float* tgt     = (const float*)d_in[0];
    const float* qp      = (const float*)d_in[1];
    const float* refpts  = (const float*)d_in[2];
    const float* src     = (const float*)d_in[3];
    const float* in_w    = (const float*)d_in[4];
    const float* in_b    = (const float*)d_in[5];
    const float* out_w   = (const float*)d_in[6];
    const float* out_b   = (const float*)d_in[7];
    const float* n2g     = (const float*)d_in[8];
    const float* n2b     = (const float*)d_in[9];
    const float* value_w = (const float*)d_in[10];
    const float* value_b = (const float*)d_in[11];
    const float* off_w   = (const float*)d_in[12];
    const float* off_b   = (const float*)d_in[13];
    const float* attw_w  = (const float*)d_in[14];
    const float* attw_b  = (const float*)d_in[15];
    const float* outp_w  = (const float*)d_in[16];
    const float* outp_b  = (const float*)d_in[17];
    const float* n1g     = (const float*)d_in[18];
    const float* n1b     = (const float*)d_in[19];
    const float* lin1_w  = (const float*)d_in[20];
    const float* lin1_b  = (const float*)d_in[21];
    const float* lin2_w  = (const float*)d_in[22];
    const float* lin2_b  = (const float*)d_in[23];
    const float* n3g     = (const float*)d_in[24];
    const float* n3b     = (const float*)d_in[25];

    // Resolve scratch symbol addresses once (host-side queries; capture-safe,
    // but hoisted out of the per-call path anyway).
    static float *p_qk, *p_v, *p_att, *p_att2, *p_t1, *p_val, *p_off,
                 *p_attw, *p_samp, *p_ms, *p_t2, *p_f1, *p_f2;
    static bool init = false;
    if (!init) {
        void* p;
        cudaGetSymbolAddress(&p, g_qk);   p_qk   = (float*)p;
        cudaGetSymbolAddress(&p, g_v);    p_v    = (float*)p;
        cudaGetSymbolAddress(&p, g_att);  p_att  = (float*)p;
        cudaGetSymbolAddress(&p, g_att2); p_att2 = (float*)p;
        cudaGetSymbolAddress(&p, g_t1);   p_t1   = (float*)p;
        cudaGetSymbolAddress(&p, g_value);p_val  = (float*)p;
        cudaGetSymbolAddress(&p, g_off);  p_off  = (float*)p;
        cudaGetSymbolAddress(&p, g_attw); p_attw = (float*)p;
        cudaGetSymbolAddress(&p, g_samp); p_samp = (float*)p;
        cudaGetSymbolAddress(&p, g_ms);   p_ms   = (float*)p;
        cudaGetSymbolAddress(&p, g_t2);   p_t2   = (float*)p;
        cudaGetSymbolAddress(&p, g_ffn1); p_f1   = (float*)p;
        cudaGetSymbolAddress(&p, g_ffn2); p_f2   = (float*)p;
        init = true;
    }

    const dim3 blk(256);

    // 1) q|k = (tgt+qp) @ in_proj_w[0:512]^T
    gemm_kernel<<<dim3(512/64, NTOK/64), blk>>>(tgt, qp, in_w, in_b, p_qk, NTOK, 256, 512, 0);
    // 2) v = tgt @ in_proj_w[512:768]^T
    gemm_kernel<<<dim3(256/64, NTOK/64), blk>>>(tgt, nullptr, in_w + (size_t)512*256, in_b + 512, p_v, NTOK, 256, 256, 0);
    // 3) attention
    attn_kernel<<<dim3(LQ/128, BB*HH), dim3(128)>>>(p_qk, p_v, p_att);
    // 4) out_proj
    gemm_kernel<<<dim3(256/64, NTOK/64), blk>>>(p_att, nullptr, out_w, out_b, p_att2, NTOK, 256, 256, 0);
    // 5) t1 = LN(tgt + att2)  [norm2]
    ln_kernel<<<NTOK/8, blk>>>(tgt, p_att2, n2g, n2b, p_t1);
    // 6) value = src @ value_w^T
    gemm_kernel<<<dim3(256/64, NV/64), blk>>>(src, nullptr, value_w, value_b, p_val, NV, 256, 256, 0);
    // 7) off = (t1+qp) @ off_w^T
    gemm_kernel<<<dim3(256/64, NTOK/64), blk>>>(p_t1, qp, off_w, off_b, p_off, NTOK, 256, 256, 0);
    // 8) attw = (t1+qp) @ attw_w^T
    gemm_kernel<<<dim3(128/64, NTOK/64), blk>>>(p_t1, qp, attw_w, attw_b, p_attw, NTOK, 256, 128, 0);
    // 9) softmax over L*P per (token,h)
    softmax16_kernel<<<(NTOK*HH + 255)/256, blk>>>(p_attw);
    // 10) bilinear sampling
    sample_kernel<<<(NTOK*HH)/8, blk>>>(refpts, p_off, p_attw, p_val, p_samp);
    // 11) output projection of deformable attn
    gemm_kernel<<<dim3(256/64, NTOK/64), blk>>>(p_samp, nullptr, outp_w, outp_b, p_ms, NTOK, 256, 256, 0);
    // 12) t2 = LN(t1 + ms)  [norm1]
    ln_kernel<<<NTOK/8, blk>>>(p_t1, p_ms, n1g, n1b, p_t2);
    // 13) ffn1 = relu(t2 @ lin1^T)
    gemm_kernel<<<dim3(1024/64, NTOK/64), blk>>>(p_t2, nullptr, lin1_w, lin1_b, p_f1, NTOK, 256, 1024, 1);
    // 14) ffn2 = ffn1 @ lin2^T
    gemm_kernel<<<dim3(256/64, NTOK/64), blk>>>(p_f1, nullptr, lin2_w, lin2_b, p_f2, NTOK, 1024, 256, 0);
    // 15) out = LN(t2 + ffn2)  [norm3]
    ln_kernel<<<NTOK/8, blk>>>(p_t2, p_f2, n3g, n3b, (float*)d_out);
}

// round 3
// speedup vs baseline: 1.0427x; 1.0427x over previous
#include <cuda_runtime.h>
#include <cuda_bf16.h>
#include <math.h>

// Problem constants
#define BB   16
#define LQ   1024
#define DD   256
#define HH   8
#define LL   4
#define PP   4
#define DFF  1024
#define LV   5440
#define DH   32
#define NTOK (BB*LQ)        // 16384
#define NV   (BB*LV)        // 87040

typedef unsigned long long ull;

// ---------------- packed f32x2 helpers (sm_103a FFMA2) -----------------------
__device__ __forceinline__ ull ffma2(ull a, ull b, ull c) {
    ull d;
    asm("fma.rn.f32x2 %0, %1, %2, %3;" : "=l"(d) : "l"(a), "l"(b), "l"(c));
    return d;
}
__device__ __forceinline__ ull pack2(float lo, float hi) {
    ull d;
    asm("mov.b64 %0, {%1, %2};" : "=l"(d)
        : "r"(__float_as_uint(lo)), "r"(__float_as_uint(hi)));
    return d;
}
__device__ __forceinline__ float2 unpack2(ull v) {
    unsigned lo, hi;
    asm("mov.b64 {%0, %1}, %2;" : "=r"(lo), "=r"(hi) : "l"(v));
    return make_float2(__uint_as_float(lo), __uint_as_float(hi));
}

// ---------------- scratch (device globals; no allocs allowed) ----------------
__device__ float g_qk  [(size_t)NTOK*512];
__device__ float g_v   [(size_t)NTOK*256];
__device__ float g_att [(size_t)NTOK*256];
__device__ float g_att2[(size_t)NTOK*256];
__device__ float g_t1  [(size_t)NTOK*256];
__device__ float g_value[(size_t)NV*256];
__device__ float g_off [(size_t)NTOK*256];
__device__ float g_attw[(size_t)NTOK*128];
__device__ float g_samp[(size_t)NTOK*256];
__device__ float g_ms  [(size_t)NTOK*256];
__device__ float g_t2  [(size_t)NTOK*256];
__device__ float g_ffn1[(size_t)NTOK*1024];
__device__ float g_ffn2[(size_t)NTOK*256];

// ---------------- GEMM: C[N,M] = (A0 (+A1)) @ W[M,K]^T + bias ---------------
// 128x128 tile, BK=8, 256 threads, 8x8 microtile via packed FFMA2.
// A is stored DUPLICATED in smem so (a_i,a_i) pairs load directly as b64.
// Requires N%128==0, M%128==0, K%8==0.
__global__ void __launch_bounds__(256, 2) gemm_kernel(
    const float* __restrict__ A0, const float* __restrict__ A1,
    const float* __restrict__ W,  const float* __restrict__ bias,
    float* __restrict__ C, int N, int K, int M, int relu)
{
    __shared__ float As2[2][8][264];   // duplicated A: [k][2i]=(a_i), [k][2i+1]=(a_i)
    __shared__ float Bs [2][8][132];

    const int tid = threadIdx.x;
    const int r0 = blockIdx.y * 128;
    const int c0 = blockIdx.x * 128;
    const int frow = tid >> 1;        // 0..127
    const int fk   = (tid & 1) * 4;   // 0 or 4
    const int ty = tid >> 4;          // 0..15 -> rows ty*8..+7
    const int tx = tid & 15;          // 0..15 -> cols tx*8..+7
    const int i0 = ty * 8;
    const int j0 = tx * 8;

    ull acc[8][4];
    #pragma unroll
    for (int i = 0; i < 8; i++)
        #pragma unroll
        for (int j = 0; j < 4; j++) acc[i][j] = 0ULL;

    const float* Aptr  = A0 + (size_t)(r0 + frow) * K + fk;
    const float* A1ptr = A1 ? (A1 + (size_t)(r0 + frow) * K + fk) : nullptr;
    const float* Wptr  = W  + (size_t)(c0 + frow) * K + fk;

    float4 avA = *(const float4*)(Aptr);
    if (A1ptr) {
        float4 t = *(const float4*)(A1ptr);
        avA.x += t.x; avA.y += t.y; avA.z += t.z; avA.w += t.w;
    }
    float4 avB = *(const float4*)(Wptr);

    int buf = 0;
    #pragma unroll 1
    for (int kt = 0; kt < K; kt += 8) {
        // store current regs to smem[buf]
        As2[buf][fk+0][2*frow] = avA.x; As2[buf][fk+0][2*frow+1] = avA.x;
        As2[buf][fk+1][2*frow] = avA.y; As2[buf][fk+1][2*frow+1] = avA.y;
        As2[buf][fk+2][2*frow] = avA.z; As2[buf][fk+2][2*frow+1] = avA.z;
        As2[buf][fk+3][2*frow] = avA.w; As2[buf][fk+3][2*frow+1] = avA.w;
        Bs[buf][fk+0][frow] = avB.x;
        Bs[buf][fk+1][frow] = avB.y;
        Bs[buf][fk+2][frow] = avB.z;
        Bs[buf][fk+3][frow] = avB.w;
        __syncthreads();

        // prefetch next k-tile
        if (kt + 8 < K) {
            avA = *(const float4*)(Aptr + kt + 8);
            if (A1ptr) {
                float4 t = *(const float4*)(A1ptr + kt + 8);
                avA.x += t.x; avA.y += t.y; avA.z += t.z; avA.w += t.w;
            }
            avB = *(const float4*)(Wptr + kt + 8);
        }

        // compute on smem[buf]
        #pragma unroll
        for (int k = 0; k < 8; k++) {
            const ulonglong2* ap = (const ulonglong2*)&As2[buf][k][2*i0];
            const ulonglong2* bp = (const ulonglong2*)&Bs[buf][k][j0];
            ulonglong2 a01 = ap[0], a23 = ap[1], a45 = ap[2], a67 = ap[3];
            ulonglong2 b03 = bp[0], b47 = bp[1];
            ull ad[8] = {a01.x, a01.y, a23.x, a23.y, a45.x, a45.y, a67.x, a67.y};
            ull bd[4] = {b03.x, b03.y, b47.x, b47.y};
            #pragma unroll
            for (int i = 0; i < 8; i++)
                #pragma unroll
                for (int j = 0; j < 4; j++)
                    acc[i][j] = ffma2(ad[i], bd[j], acc[i][j]);
        }
        buf ^= 1;
    }

    // epilogue
    float4 bi0 = *(const float4*)(bias + c0 + j0);
    float4 bi1 = *(const float4*)(bias + c0 + j0 + 4);
    #pragma unroll
    for (int i = 0; i < 8; i++) {
        const size_t row = (size_t)(r0 + i0 + i);
        float2 p0 = unpack2(acc[i][0]);
        float2 p1 = unpack2(acc[i][1]);
        float2 p2 = unpack2(acc[i][2]);
        float2 p3 = unpack2(acc[i][3]);
        float4 o0, o1;
        o0.x = p0.x + bi0.x; o0.y = p0.y + bi0.y;
        o0.z = p1.x + bi0.z; o0.w = p1.y + bi0.w;
        o1.x = p2.x + bi1.x; o1.y = p2.y + bi1.y;
        o1.z = p3.x + bi1.z; o1.w = p3.y + bi1.w;
        if (relu) {
            o0.x = fmaxf(o0.x, 0.f); o0.y = fmaxf(o0.y, 0.f);
            o0.z = fmaxf(o0.z, 0.f); o0.w = fmaxf(o0.w, 0.f);
            o1.x = fmaxf(o1.x, 0.f); o1.y = fmaxf(o1.y, 0.f);
            o1.z = fmaxf(o1.z, 0.f); o1.w = fmaxf(o1.w, 0.f);
        }
        *(float4*)(C + row * M + c0 + j0)     = o0;
        *(float4*)(C + row * M + c0 + j0 + 4) = o1;
    }
}

// ---------------- flash attention: one query per thread, FFMA2 ---------------
// QK: [NTOK,512] (q | k), V: [NTOK,256]. grid (LQ/128, B*H), 128 threads.
__global__ void __launch_bounds__(128) attn_kernel(
    const float* __restrict__ QK, const float* __restrict__ V, float* __restrict__ O)
{
    const int bh = blockIdx.y;
    const int b = bh >> 3, h = bh & 7;
    const int tid = threadIdx.x;
    const int qi = blockIdx.x * 128 + tid;

    ull q2[16];
    {
        const size_t qrow = ((size_t)b * LQ + qi) * 512 + h * 32;
        const ulonglong2* qp = (const ulonglong2*)(QK + qrow);
        #pragma unroll
        for (int d8 = 0; d8 < 8; d8++) {
            ulonglong2 t = qp[d8];
            q2[2*d8] = t.x; q2[2*d8+1] = t.y;
        }
    }
    __shared__ float Ks[32][32];
    __shared__ float Vs[32][32];

    ull o2[16];
    #pragma unroll
    for (int d = 0; d < 16; d++) o2[d] = 0ULL;
    float m = -1e30f, lsum = 0.f;
    const float scale = 0.17677669529663687f;   // 1/sqrt(32)

    const size_t kbase = ((size_t)b * LQ) * 512 + 256 + h * 32;
    const size_t vbase = ((size_t)b * LQ) * 256 + h * 32;

    for (int kt = 0; kt < LQ; kt += 32) {
        __syncthreads();
        #pragma unroll
        for (int i = 0; i < 2; i++) {
            const int f4  = tid * 2 + i;       // 0..255
            const int key = f4 >> 3;
            const int d4  = (f4 & 7) * 4;
            *(float4*)&Ks[key][d4] = *(const float4*)(QK + kbase + (size_t)(kt + key) * 512 + d4);
            *(float4*)&Vs[key][d4] = *(const float4*)(V  + vbase + (size_t)(kt + key) * 256 + d4);
        }
        __syncthreads();

        float s[32];
        #pragma unroll
        for (int key = 0; key < 32; key++) {
            const ulonglong2* kp = (const ulonglong2*)Ks[key];
            ull accA = 0ULL, accB = 0ULL;
            #pragma unroll
            for (int d8 = 0; d8 < 4; d8++) {
                ulonglong2 kv = kp[d8];
                accA = ffma2(q2[2*d8],   kv.x, accA);
                accB = ffma2(q2[2*d8+1], kv.y, accB);
            }
            const ulonglong2* kp2 = kp + 4;
            #pragma unroll
            for (int d8 = 0; d8 < 4; d8++) {
                ulonglong2 kv = kp2[d8];
                accA = ffma2(q2[8+2*d8],   kv.x, accA);
                accB = ffma2(q2[8+2*d8+1], kv.y, accB);
            }
            float2 fa = unpack2(accA), fb = unpack2(accB);
            s[key] = (fa.x + fa.y + fb.x + fb.y) * scale;
        }
        float tmax = s[0];
        #pragma unroll
        for (int key = 1; key < 32; key++) tmax = fmaxf(tmax, s[key]);
        const float mn = fmaxf(m, tmax);
        const float corr = __expf(m - mn);
        lsum *= corr;
        const ull corrd = pack2(corr, corr);
        #pragma unroll
        for (int d = 0; d < 16; d++) o2[d] = ffma2(corrd, o2[d], 0ULL);
        #pragma unroll
        for (int key = 0; key < 32; key++) {
            const float p = __expf(s[key] - mn);
            lsum += p;
            const ull pd = pack2(p, p);
            const ulonglong2* vp = (const ulonglong2*)Vs[key];
            #pragma unroll
            for (int d8 = 0; d8 < 8; d8++) {
                ulonglong2 vv = vp[d8];
                o2[2*d8]   = ffma2(pd, vv.x, o2[2*d8]);
                o2[2*d8+1] = ffma2(pd, vv.y, o2[2*d8+1]);
            }
        }
        m = mn;
    }
    const float inv = 1.f / lsum;
    const size_t orow = ((size_t)b * LQ + qi) * 256 + h * 32;
    #pragma unroll
    for (int d8 = 0; d8 < 8; d8++) {
        float2 lo = unpack2(o2[2*d8]);
        float2 hi = unpack2(o2[2*d8+1]);
        float4 t;
        t.x = lo.x * inv; t.y = lo.y * inv;
        t.z = hi.x * inv; t.w = hi.y * inv;
        *(float4*)(O + orow + d8*4) = t;
    }
}

// ---------------- residual + layernorm: Y = LN(A + Bres) ---------------------
__global__ void __launch_bounds__(256) ln_kernel(
    const float* __restrict__ A, const float* __restrict__ Bres,
    const float* __restrict__ g, const float* __restrict__ beta,
    float* __restrict__ Y)
{
    const int warp = threadIdx.x >> 5, lane = threadIdx.x & 31;
    const size_t row = (size_t)blockIdx.x * 8 + warp;
    const float* a = A    + row * 256;
    const float* b = Bres + row * 256;
    float v[8];
    #pragma unroll
    for (int i = 0; i < 2; i++) {
        float4 x = *(const float4*)(a + i*128 + lane*4);
        float4 y = *(const float4*)(b + i*128 + lane*4);
        v[i*4+0] = x.x + y.x; v[i*4+1] = x.y + y.y;
        v[i*4+2] = x.z + y.z; v[i*4+3] = x.w + y.w;
    }
    float sum = 0.f, sq = 0.f;
    #pragma unroll
    for (int i = 0; i < 8; i++) { sum += v[i]; sq = fmaf(v[i], v[i], sq); }
    #pragma unroll
    for (int off = 16; off > 0; off >>= 1) {
        sum += __shfl_xor_sync(0xffffffffu, sum, off);
        sq  += __shfl_xor_sync(0xffffffffu, sq,  off);
    }
    const float mean = sum * (1.f/256.f);
    const float var  = sq * (1.f/256.f) - mean * mean;
    const float inv  = rsqrtf(var + 1e-5f);
    #pragma unroll
    for (int i = 0; i < 2; i++) {
        const int col = i*128 + lane*4;
        float4 gg = *(const float4*)(g + col);
        float4 bb = *(const float4*)(beta + col);
        float4 out;
        out.x = (v[i*4+0]-mean)*inv*gg.x + bb.x;
        out.y = (v[i*4+1]-mean)*inv*gg.y + bb.y;
        out.z = (v[i*4+2]-mean)*inv*gg.z + bb.z;
        out.w = (v[i*4+3]-mean)*inv*gg.w + bb.w;
        *(float4*)(Y + row*256 + col) = out;
    }
}

// ---------------- softmax over 16 contiguous values per (token,h) ------------
__global__ void __launch_bounds__(256) softmax16_kernel(float* __restrict__ W)
{
    const int tid = blockIdx.x * 256 + threadIdx.x;
    if (tid >= NTOK * HH) return;
    float* p = W + (size_t)tid * 16;
    float v[16];
    #pragma unroll
    for (int i = 0; i < 4; i++) {
        float4 t = *(const float4*)(p + i*4);
        v[i*4+0]=t.x; v[i*4+1]=t.y; v[i*4+2]=t.z; v[i*4+3]=t.w;
    }
    float mx = v[0];
    #pragma unroll
    for (int i = 1; i < 16; i++) mx = fmaxf(mx, v[i]);
    float s = 0.f;
    #pragma unroll
    for (int i = 0; i < 16; i++) { v[i] = __expf(v[i]-mx); s += v[i]; }
    const float inv = 1.f / s;
    #pragma unroll
    for (int i = 0; i < 4; i++) {
        float4 t;
        t.x=v[i*4+0]*inv; t.y=v[i*4+1]*inv; t.z=v[i*4+2]*inv; t.w=v[i*4+3]*inv;
        *(float4*)(p + i*4) = t;
    }
}

// ---------------- deformable bilinear sampling -------------------------------
__device__ __forceinline__ float fetch_v(const float* __restrict__ value, size_t vb,
                                         int start, int WL2, int HL2, int xi, int yi)
{
    const bool ok = ((unsigned)xi < (unsigned)WL2) & ((unsigned)yi < (unsigned)HL2);
    const int xc = min(max(xi, 0), WL2 - 1);
    const int yc = min(max(yi, 0), HL2 - 1);
    const float val = value[vb + (size_t)(start + yc * WL2 + xc) * 256];
    return ok ? val : 0.f;
}

__global__ void __launch_bounds__(256) sample_kernel(
    const float* __restrict__ ref, const float* __restrict__ off,
    const float* __restrict__ attw, const float* __restrict__ value,
    float* __restrict__ out)
{
    const int wg   = blockIdx.x * 8 + (threadIdx.x >> 5);
    const int lane = threadIdx.x & 31;
    const int h  = wg & 7;
    const int tq = wg >> 3;            // b*LQ + q
    const int b  = tq >> 10;

    const float* refp = ref  + (size_t)tq * (LL*2);
    const float* offp = off  + (size_t)tq * 256 + h * 32;
    const float* awp  = attw + (size_t)tq * 128 + h * 16;
    const size_t vb   = ((size_t)b * LV) * 256 + h * 32 + lane;

    const int wls[4]    = {64, 32, 16, 8};
    const int hls[4]    = {64, 32, 16, 8};
    const int starts[4] = {0, 4096, 5120, 5376};

    float acc = 0.f;
    #pragma unroll
    for (int l = 0; l < 4; l++) {
        const int WL2 = wls[l], HL2 = hls[l], st = starts[l];
        const float rx = refp[l*2], ry = refp[l*2+1];
        #pragma unroll
        for (int p = 0; p < 4; p++) {
            const float ox = offp[(l*4+p)*2];
            const float oy = offp[(l*4+p)*2+1];
            const float aw = awp[l*4+p];
            const float x = fmaf(rx, (float)WL2, ox) - 0.5f;
            const float y = fmaf(ry, (float)HL2, oy) - 0.5f;
            const float xf = floorf(x), yf = floorf(y);
            const float lx = x - xf, ly = y - yf;
            const int x0 = (int)xf, y0 = (int)yf;
            const float v00 = fetch_v(value, vb, st, WL2, HL2, x0,   y0);
            const float v01 = fetch_v(value, vb, st, WL2, HL2, x0+1, y0);
            const float v10 = fetch_v(value, vb, st, WL2, HL2, x0,   y0+1);
            const float v11 = fetch_v(value, vb, st, WL2, HL2, x0+1, y0+1);
            const float top = v00 + lx * (v01 - v00);
            const float bot = v10 + lx * (v11 - v10);
            acc = fmaf(aw, top + ly * (bot - top), acc);
        }
    }
    out[(size_t)tq * 256 + h * 32 + lane] = acc;
}

// ---------------- host orchestration -----------------------------------------
extern "C" void kernel_launch(void* const* d_in, const int* in_sizes, int n_in,
                              void* d_out, int out_size)
{
    const float* tgt     = (const float*)d_in[0];
    const float* qp      = (const float*)d_in[1];
    const float* refpts  = (const float*)d_in[2];
    const float* src     = (const float*)d_in[3];
    const float* in_w    = (const float*)d_in[4];
    const float* in_b    = (const float*)d_in[5];
    const float* out_w   = (const float*)d_in[6];
    const float* out_b   = (const float*)d_in[7];
    const float* n2g     = (const float*)d_in[8];
    const float* n2b     = (const float*)d_in[9];
    const float* value_w = (const float*)d_in[10];
    const float* value_b = (const float*)d_in[11];
    const float* off_w   = (const float*)d_in[12];
    const float* off_b   = (const float*)d_in[13];
    const float* attw_w  = (const float*)d_in[14];
    const float* attw_b  = (const float*)d_in[15];
    const float* outp_w  = (const float*)d_in[16];
    const float* outp_b  = (const float*)d_in[17];
    const float* n1g     = (const float*)d_in[18];
    const float* n1b     = (const float*)d_in[19];
    const float* lin1_w  = (const float*)d_in[20];
    const float* lin1_b  = (const float*)d_in[21];
    const float* lin2_w  = (const float*)d_in[22];
    const float* lin2_b  = (const float*)d_in[23];
    const float* n3g     = (const float*)d_in[24];
    const float* n3b     = (const float*)d_in[25];

    static float *p_qk, *p_v, *p_att, *p_att2, *p_t1, *p_val, *p_off,
                 *p_attw, *p_samp, *p_ms, *p_t2, *p_f1, *p_f2;
    static bool init = false;
    if (!init) {
        void* p;
        cudaGetSymbolAddress(&p, g_qk);   p_qk   = (float*)p;
        cudaGetSymbolAddress(&p, g_v);    p_v    = (float*)p;
        cudaGetSymbolAddress(&p, g_att);  p_att  = (float*)p;
        cudaGetSymbolAddress(&p, g_att2); p_att2 = (float*)p;
        cudaGetSymbolAddress(&p, g_t1);   p_t1   = (float*)p;
        cudaGetSymbolAddress(&p, g_value);p_val  = (float*)p;
        cudaGetSymbolAddress(&p, g_off);  p_off  = (float*)p;
        cudaGetSymbolAddress(&p, g_attw); p_attw = (float*)p;
        cudaGetSymbolAddress(&p, g_samp); p_samp = (float*)p;
        cudaGetSymbolAddress(&p, g_ms);   p_ms   = (float*)p;
        cudaGetSymbolAddress(&p, g_t2);   p_t2   = (float*)p;
        cudaGetSymbolAddress(&p, g_ffn1); p_f1   = (float*)p;
        cudaGetSymbolAddress(&p, g_ffn2); p_f2   = (float*)p;
        init = true;
    }

    const dim3 blk(256);

    // 1) q|k = (tgt+qp) @ in_proj_w[0:512]^T
    gemm_kernel<<<dim3(512/128, NTOK/128), blk>>>(tgt, qp, in_w, in_b, p_qk, NTOK, 256, 512, 0);
    // 2) v = tgt @ in_proj_w[512:768]^T
    gemm_kernel<<<dim3(256/128, NTOK/128), blk>>>(tgt, nullptr, in_w + (size_t)512*256, in_b + 512, p_v, NTOK, 256, 256, 0);
    // 3) attention
    attn_kernel<<<dim3(LQ/128, BB*HH), dim3(128)>>>(p_qk, p_v, p_att);
    // 4) out_proj
    gemm_kernel<<<dim3(256/128, NTOK/128), blk>>>(p_att, nullptr, out_w, out_b, p_att2, NTOK, 256, 256, 0);
    // 5) t1 = LN(tgt + att2)  [norm2]
    ln_kernel<<<NTOK/8, blk>>>(tgt, p_att2, n2g, n2b, p_t1);
    // 6) value = src @ value_w^T
    gemm_kernel<<<dim3(256/128, NV/128), blk>>>(src, nullptr, value_w, value_b, p_val, NV, 256, 256, 0);
    // 7) off = (t1+qp) @ off_w^T
    gemm_kernel<<<dim3(256/128, NTOK/128), blk>>>(p_t1, qp, off_w, off_b, p_off, NTOK, 256, 256, 0);
    // 8) attw = (t1+qp) @ attw_w^T
    gemm_kernel<<<dim3(128/128, NTOK/128), blk>>>(p_t1, qp, attw_w, attw_b, p_attw, NTOK, 256, 128, 0);
    // 9) softmax over L*P per (token,h)
    softmax16_kernel<<<(NTOK*HH + 255)/256, blk>>>(p_attw);
    // 10) bilinear sampling
    sample_kernel<<<(NTOK*HH)/8, blk>>>(refpts, p_off, p_attw, p_val, p_samp);
    // 11) output projection of deformable attn
    gemm_kernel<<<dim3(256/128, NTOK/128), blk>>>(p_samp, nullptr, outp_w, outp_b, p_ms, NTOK, 256, 256, 0);
    // 12) t2 = LN(t1 + ms)  [norm1]
    ln_kernel<<<NTOK/8, blk>>>(p_t1, p_ms, n1g, n1b, p_t2);
    // 13) ffn1 = relu(t2 @ lin1^T)
    gemm_kernel<<<dim3(1024/128, NTOK/128), blk>>>(p_t2, nullptr, lin1_w, lin1_b, p_f1, NTOK, 256, 1024, 1);
    // 14) ffn2 = ffn1 @ lin2^T
    gemm_kernel<<<dim3(256/128, NTOK/128), blk>>>(p_f1, nullptr, lin2_w, lin2_b, p_f2, NTOK, 1024, 256, 0);
    // 15) out = LN(t2 + ffn2)  [norm3]
    ln_kernel<<<NTOK/8, blk>>>(p_t2, p_f2, n3g, n3b, (float*)d_out);
}

// round 4
// speedup vs baseline: 1.5626x; 1.4986x over previous
#include <cuda_runtime.h>
#include <cuda_bf16.h>
#include <math.h>

// Problem constants
#define BB   16
#define LQ   1024
#define DD   256
#define HH   8
#define LL   4
#define PP   4
#define DFF  1024
#define LV   5440
#define DH   32
#define NTOK (BB*LQ)        // 16384
#define NV   (BB*LV)        // 87040

typedef unsigned long long ull;

// ---------------- packed f32x2 helpers (used by attention) -------------------
__device__ __forceinline__ ull ffma2(ull a, ull b, ull c) {
    ull d;
    asm("fma.rn.f32x2 %0, %1, %2, %3;" : "=l"(d) : "l"(a), "l"(b), "l"(c));
    return d;
}
__device__ __forceinline__ ull pack2(float lo, float hi) {
    ull d;
    asm("mov.b64 %0, {%1, %2};" : "=l"(d)
        : "r"(__float_as_uint(lo)), "r"(__float_as_uint(hi)));
    return d;
}
__device__ __forceinline__ float2 unpack2(ull v) {
    unsigned lo, hi;
    asm("mov.b64 {%0, %1}, %2;" : "=r"(lo), "=r"(hi) : "l"(v));
    return make_float2(__uint_as_float(lo), __uint_as_float(hi));
}
__device__ __forceinline__ unsigned f2tf32(float f) {
    unsigned r;
    asm("cvt.rna.tf32.f32 %0, %1;" : "=r"(r) : "f"(f));
    return r;
}

// ---------------- scratch (device globals; no allocs allowed) ----------------
__device__ float g_qk  [(size_t)NTOK*512];
__device__ float g_v   [(size_t)NTOK*256];
__device__ float g_att [(size_t)NTOK*256];
__device__ float g_att2[(size_t)NTOK*256];
__device__ float g_t1  [(size_t)NTOK*256];
__device__ float g_value[(size_t)NV*256];
__device__ float g_off [(size_t)NTOK*256];
__device__ float g_attw[(size_t)NTOK*128];
__device__ float g_samp[(size_t)NTOK*256];
__device__ float g_ms  [(size_t)NTOK*256];
__device__ float g_t2  [(size_t)NTOK*256];
__device__ float g_ffn1[(size_t)NTOK*1024];
__device__ float g_ffn2[(size_t)NTOK*256];

// ---------------- tensor-core GEMM (tf32 mma.sync) ---------------------------
// C[N,M] = (A0 (+A1))[N,K] @ W[M,K]^T + bias  (optional relu)
// 128x128 block tile, KC=32, 256 threads = 8 warps laid out 2(row)x4(col),
// each warp computes 64x32 via 4x4 grid of m16n8k8 tf32 MMAs.
// smem layout: per row, each k8-group stored pair-permuted:
//   group positions [0..7] hold k = 0,4,1,5,2,6,3,7  (so (k, k+4) are adjacent
//   -> every fragment pair is one LDS.64)
// Requires N%128==0, M%128==0, K%32==0.
#define GSTRIDE 36
__global__ void __launch_bounds__(256, 2) gemm_tc(
    const float* __restrict__ A0, const float* __restrict__ A1,
    const float* __restrict__ W,  const float* __restrict__ bias,
    float* __restrict__ C, int N, int K, int M, int relu)
{
    __shared__ unsigned As[128][GSTRIDE];
    __shared__ unsigned Bs[128][GSTRIDE];

    const int tid  = threadIdx.x;
    const int lane = tid & 31;
    const int wid  = tid >> 5;
    const int wr   = wid & 1;          // warp row: 0/1 -> rows 0..63 / 64..127
    const int wc   = wid >> 1;         // warp col: 0..3 -> cols 32*wc
    const int g    = lane >> 2;        // groupID 0..7
    const int tig  = lane & 3;         // thread-in-group 0..3
    const int r0 = blockIdx.y * 128;
    const int c0 = blockIdx.x * 128;

    float acc[4][4][4];                // [mt][nt][c0..c3]
    #pragma unroll
    for (int mt = 0; mt < 4; mt++)
        #pragma unroll
        for (int nt = 0; nt < 4; nt++)
            #pragma unroll
            for (int c = 0; c < 4; c++) acc[mt][nt][c] = 0.f;

    const int frow = tid >> 1;         // 0..127
    const int fk8  = tid & 1;          // half of each 8-group
    const float* Ap  = A0 + (size_t)(r0 + frow) * K;
    const float* A1p = A1 ? (A1 + (size_t)(r0 + frow) * K) : nullptr;
    const float* Wp  = W  + (size_t)(c0 + frow) * K;

    for (int kt = 0; kt < K; kt += 32) {
        __syncthreads();
        #pragma unroll
        for (int it = 0; it < 4; it++) {
            const int ksrc = kt + it * 8 + fk8 * 4;
            float4 a = *(const float4*)(Ap + ksrc);
            if (A1p) {
                float4 t = *(const float4*)(A1p + ksrc);
                a.x += t.x; a.y += t.y; a.z += t.z; a.w += t.w;
            }
            float4 b = *(const float4*)(Wp + ksrc);
            const int d = it * 8 + fk8;     // positions d, d+2, d+4, d+6
            As[frow][d+0] = f2tf32(a.x);
            As[frow][d+2] = f2tf32(a.y);
            As[frow][d+4] = f2tf32(a.z);
            As[frow][d+6] = f2tf32(a.w);
            Bs[frow][d+0] = f2tf32(b.x);
            Bs[frow][d+2] = f2tf32(b.y);
            Bs[frow][d+4] = f2tf32(b.z);
            Bs[frow][d+6] = f2tf32(b.w);
        }
        __syncthreads();

        #pragma unroll
        for (int k8 = 0; k8 < 4; k8++) {
            unsigned af[4][4];
            #pragma unroll
            for (int mt = 0; mt < 4; mt++) {
                const int rowa = wr * 64 + mt * 16 + g;
                uint2 p0 = *(const uint2*)&As[rowa    ][k8 * 8 + 2 * tig]; // a0,a2
                uint2 p1 = *(const uint2*)&As[rowa + 8][k8 * 8 + 2 * tig]; // a1,a3
                af[mt][0] = p0.x; af[mt][1] = p1.x; af[mt][2] = p0.y; af[mt][3] = p1.y;
            }
            unsigned bf[4][2];
            #pragma unroll
            for (int nt = 0; nt < 4; nt++) {
                const int coln = wc * 32 + nt * 8 + g;
                uint2 p = *(const uint2*)&Bs[coln][k8 * 8 + 2 * tig];      // b0,b1
                bf[nt][0] = p.x; bf[nt][1] = p.y;
            }
            #pragma unroll
            for (int mt = 0; mt < 4; mt++)
                #pragma unroll
                for (int nt = 0; nt < 4; nt++)
                    asm volatile(
                        "mma.sync.aligned.m16n8k8.row.col.f32.tf32.tf32.f32 "
                        "{%0,%1,%2,%3}, {%4,%5,%6,%7}, {%8,%9}, {%0,%1,%2,%3};"
                        : "+f"(acc[mt][nt][0]), "+f"(acc[mt][nt][1]),
                          "+f"(acc[mt][nt][2]), "+f"(acc[mt][nt][3])
                        : "r"(af[mt][0]), "r"(af[mt][1]), "r"(af[mt][2]), "r"(af[mt][3]),
                          "r"(bf[nt][0]), "r"(bf[nt][1]));
        }
    }

    // epilogue: c0=C[g][2t], c1=C[g][2t+1], c2=C[g+8][2t], c3=C[g+8][2t+1]
    #pragma unroll
    for (int nt = 0; nt < 4; nt++) {
        const int col = c0 + wc * 32 + nt * 8 + 2 * tig;
        float2 bi = *(const float2*)(bias + col);
        #pragma unroll
        for (int mt = 0; mt < 4; mt++) {
            const int row = r0 + wr * 64 + mt * 16 + g;
            float2 lo, hi;
            lo.x = acc[mt][nt][0] + bi.x; lo.y = acc[mt][nt][1] + bi.y;
            hi.x = acc[mt][nt][2] + bi.x; hi.y = acc[mt][nt][3] + bi.y;
            if (relu) {
                lo.x = fmaxf(lo.x, 0.f); lo.y = fmaxf(lo.y, 0.f);
                hi.x = fmaxf(hi.x, 0.f); hi.y = fmaxf(hi.y, 0.f);
            }
            *(float2*)(C + (size_t)row * M + col)       = lo;
            *(float2*)(C + (size_t)(row + 8) * M + col) = hi;
        }
    }
}

// ---------------- flash attention: one query per thread, FFMA2 ---------------
// QK: [NTOK,512] (q | k), V: [NTOK,256]. grid (LQ/128, B*H), 128 threads.
__global__ void __launch_bounds__(128) attn_kernel(
    const float* __restrict__ QK, const float* __restrict__ V, float* __restrict__ O)
{
    const int bh = blockIdx.y;
    const int b = bh >> 3, h = bh & 7;
    const int tid = threadIdx.x;
    const int qi = blockIdx.x * 128 + tid;

    ull q2[16];
    {
        const size_t qrow = ((size_t)b * LQ + qi) * 512 + h * 32;
        const ulonglong2* qp = (const ulonglong2*)(QK + qrow);
        #pragma unroll
        for (int d8 = 0; d8 < 8; d8++) {
            ulonglong2 t = qp[d8];
            q2[2*d8] = t.x; q2[2*d8+1] = t.y;
        }
    }
    __shared__ float Ks[32][32];
    __shared__ float Vs[32][32];

    ull o2[16];
    #pragma unroll
    for (int d = 0; d < 16; d++) o2[d] = 0ULL;
    float m = -1e30f, lsum = 0.f;
    const float scale = 0.17677669529663687f;   // 1/sqrt(32)

    const size_t kbase = ((size_t)b * LQ) * 512 + 256 + h * 32;
    const size_t vbase = ((size_t)b * LQ) * 256 + h * 32;

    for (int kt = 0; kt < LQ; kt += 32) {
        __syncthreads();
        #pragma unroll
        for (int i = 0; i < 2; i++) {
            const int f4  = tid * 2 + i;       // 0..255
            const int key = f4 >> 3;
            const int d4  = (f4 & 7) * 4;
            *(float4*)&Ks[key][d4] = *(const float4*)(QK + kbase + (size_t)(kt + key) * 512 + d4);
            *(float4*)&Vs[key][d4] = *(const float4*)(V  + vbase + (size_t)(kt + key) * 256 + d4);
        }
        __syncthreads();

        float s[32];
        #pragma unroll
        for (int key = 0; key < 32; key++) {
            const ulonglong2* kp = (const ulonglong2*)Ks[key];
            ull accA = 0ULL, accB = 0ULL;
            #pragma unroll
            for (int d8 = 0; d8 < 4; d8++) {
                ulonglong2 kv = kp[d8];
                accA = ffma2(q2[2*d8],   kv.x, accA);
                accB = ffma2(q2[2*d8+1], kv.y, accB);
            }
            const ulonglong2* kp2 = kp + 4;
            #pragma unroll
            for (int d8 = 0; d8 < 4; d8++) {
                ulonglong2 kv = kp2[d8];
                accA = ffma2(q2[8+2*d8],   kv.x, accA);
                accB = ffma2(q2[8+2*d8+1], kv.y, accB);
            }
            float2 fa = unpack2(accA), fb = unpack2(accB);
            s[key] = (fa.x + fa.y + fb.x + fb.y) * scale;
        }
        float tmax = s[0];
        #pragma unroll
        for (int key = 1; key < 32; key++) tmax = fmaxf(tmax, s[key]);
        const float mn = fmaxf(m, tmax);
        const float corr = __expf(m - mn);
        lsum *= corr;
        const ull corrd = pack2(corr, corr);
        #pragma unroll
        for (int d = 0; d < 16; d++) o2[d] = ffma2(corrd, o2[d], 0ULL);
        #pragma unroll
        for (int key = 0; key < 32; key++) {
            const float p = __expf(s[key] - mn);
            lsum += p;
            const ull pd = pack2(p, p);
            const ulonglong2* vp = (const ulonglong2*)Vs[key];
            #pragma unroll
            for (int d8 = 0; d8 < 8; d8++) {
                ulonglong2 vv = vp[d8];
                o2[2*d8]   = ffma2(pd, vv.x, o2[2*d8]);
                o2[2*d8+1] = ffma2(pd, vv.y, o2[2*d8+1]);
            }
        }
        m = mn;
    }
    const float inv = 1.f / lsum;
    const size_t orow = ((size_t)b * LQ + qi) * 256 + h * 32;
    #pragma unroll
    for (int d8 = 0; d8 < 8; d8++) {
        float2 lo = unpack2(o2[2*d8]);
        float2 hi = unpack2(o2[2*d8+1]);
        float4 t;
        t.x = lo.x * inv; t.y = lo.y * inv;
        t.z = hi.x * inv; t.w = hi.y * inv;
        *(float4*)(O + orow + d8*4) = t;
    }
}

// ---------------- residual + layernorm: Y = LN(A + Bres) ---------------------
__global__ void __launch_bounds__(256) ln_kernel(
    const float* __restrict__ A, const float* __restrict__ Bres,
    const float* __restrict__ g, const float* __restrict__ beta,
    float* __restrict__ Y)
{
    const int warp = threadIdx.x >> 5, lane = threadIdx.x & 31;
    const size_t row = (size_t)blockIdx.x * 8 + warp;
    const float* a = A    + row * 256;
    const float* b = Bres + row * 256;
    float v[8];
    #pragma unroll
    for (int i = 0; i < 2; i++) {
        float4 x = *(const float4*)(a + i*128 + lane*4);
        float4 y = *(const float4*)(b + i*128 + lane*4);
        v[i*4+0] = x.x + y.x; v[i*4+1] = x.y + y.y;
        v[i*4+2] = x.z + y.z; v[i*4+3] = x.w + y.w;
    }
    float sum = 0.f, sq = 0.f;
    #pragma unroll
    for (int i = 0; i < 8; i++) { sum += v[i]; sq = fmaf(v[i], v[i], sq); }
    #pragma unroll
    for (int off = 16; off > 0; off >>= 1) {
        sum += __shfl_xor_sync(0xffffffffu, sum, off);
        sq  += __shfl_xor_sync(0xffffffffu, sq,  off);
    }
    const float mean = sum * (1.f/256.f);
    const float var  = sq * (1.f/256.f) - mean * mean;
    const float inv  = rsqrtf(var + 1e-5f);
    #pragma unroll
    for (int i = 0; i < 2; i++) {
        const int col = i*128 + lane*4;
        float4 gg = *(const float4*)(g + col);
        float4 bb = *(const float4*)(beta + col);
        float4 out;
        out.x = (v[i*4+0]-mean)*inv*gg.x + bb.x;
        out.y = (v[i*4+1]-mean)*inv*gg.y + bb.y;
        out.z = (v[i*4+2]-mean)*inv*gg.z + bb.z;
        out.w = (v[i*4+3]-mean)*inv*gg.w + bb.w;
        *(float4*)(Y + row*256 + col) = out;
    }
}

// ---------------- softmax over 16 contiguous values per (token,h) ------------
__global__ void __launch_bounds__(256) softmax16_kernel(float* __restrict__ W)
{
    const int tid = blockIdx.x * 256 + threadIdx.x;
    if (tid >= NTOK * HH) return;
    float* p = W + (size_t)tid * 16;
    float v[16];
    #pragma unroll
    for (int i = 0; i < 4; i++) {
        float4 t = *(const float4*)(p + i*4);
        v[i*4+0]=t.x; v[i*4+1]=t.y; v[i*4+2]=t.z; v[i*4+3]=t.w;
    }
    float mx = v[0];
    #pragma unroll
    for (int i = 1; i < 16; i++) mx = fmaxf(mx, v[i]);
    float s = 0.f;
    #pragma unroll
    for (int i = 0; i < 16; i++) { v[i] = __expf(v[i]-mx); s += v[i]; }
    const float inv = 1.f / s;
    #pragma unroll
    for (int i = 0; i < 4; i++) {
        float4 t;
        t.x=v[i*4+0]*inv; t.y=v[i*4+1]*inv; t.z=v[i*4+2]*inv; t.w=v[i*4+3]*inv;
        *(float4*)(p + i*4) = t;
    }
}

// ---------------- deformable bilinear sampling -------------------------------
__device__ __forceinline__ float fetch_v(const float* __restrict__ value, size_t vb,
                                         int start, int WL2, int HL2, int xi, int yi)
{
    const bool ok = ((unsigned)xi < (unsigned)WL2) & ((unsigned)yi < (unsigned)HL2);
    const int xc = min(max(xi, 0), WL2 - 1);
    const int yc = min(max(yi, 0), HL2 - 1);
    const float val = value[vb + (size_t)(start + yc * WL2 + xc) * 256];
    return ok ? val : 0.f;
}

__global__ void __launch_bounds__(256) sample_kernel(
    const float* __restrict__ ref, const float* __restrict__ off,
    const float* __restrict__ attw, const float* __restrict__ value,
    float* __restrict__ out)
{
    const int wg   = blockIdx.x * 8 + (threadIdx.x >> 5);
    const int lane = threadIdx.x & 31;
    const int h  = wg & 7;
    const int tq = wg >> 3;            // b*LQ + q
    const int b  = tq >> 10;

    const float* refp = ref  + (size_t)tq * (LL*2);
    const float* offp = off  + (size_t)tq * 256 + h * 32;
    const float* awp  = attw + (size_t)tq * 128 + h * 16;
    const size_t vb   = ((size_t)b * LV) * 256 + h * 32 + lane;

    const int wls[4]    = {64, 32, 16, 8};
    const int hls[4]    = {64, 32, 16, 8};
    const int starts[4] = {0, 4096, 5120, 5376};

    float acc = 0.f;
    #pragma unroll
    for (int l = 0; l < 4; l++) {
        const int WL2 = wls[l], HL2 = hls[l], st = starts[l];
        const float rx = refp[l*2], ry = refp[l*2+1];
        #pragma unroll
        for (int p = 0; p < 4; p++) {
            const float ox = offp[(l*4+p)*2];
            const float oy = offp[(l*4+p)*2+1];
            const float aw = awp[l*4+p];
            const float x = fmaf(rx, (float)WL2, ox) - 0.5f;
            const float y = fmaf(ry, (float)HL2, oy) - 0.5f;
            const float xf = floorf(x), yf = floorf(y);
            const float lx = x - xf, ly = y - yf;
            const int x0 = (int)xf, y0 = (int)yf;
            const float v00 = fetch_v(value, vb, st, WL2, HL2, x0,   y0);
            const float v01 = fetch_v(value, vb, st, WL2, HL2, x0+1, y0);
            const float v10 = fetch_v(value, vb, st, WL2, HL2, x0,   y0+1);
            const float v11 = fetch_v(value, vb, st, WL2, HL2, x0+1, y0+1);
            const float top = v00 + lx * (v01 - v00);
            const float bot = v10 + lx * (v11 - v10);
            acc = fmaf(aw, top + ly * (bot - top), acc);
        }
    }
    out[(size_t)tq * 256 + h * 32 + lane] = acc;
}

// ---------------- host orchestration -----------------------------------------
extern "C" void kernel_launch(void* const* d_in, const int* in_sizes, int n_in,
                              void* d_out, int out_size)
{
    const float* tgt     = (const float*)d_in[0];
    const float* qp      = (const float*)d_in[1];
    const float* refpts  = (const float*)d_in[2];
    const float* src     = (const float*)d_in[3];
    const float* in_w    = (const float*)d_in[4];
    const float* in_b    = (const float*)d_in[5];
    const float* out_w   = (const float*)d_in[6];
    const float* out_b   = (const float*)d_in[7];
    const float* n2g     = (const float*)d_in[8];
    const float* n2b     = (const float*)d_in[9];
    const float* value_w = (const float*)d_in[10];
    const float* value_b = (const float*)d_in[11];
    const float* off_w   = (const float*)d_in[12];
    const float* off_b   = (const float*)d_in[13];
    const float* attw_w  = (const float*)d_in[14];
    const float* attw_b  = (const float*)d_in[15];
    const float* outp_w  = (const float*)d_in[16];
    const float* outp_b  = (const float*)d_in[17];
    const float* n1g     = (const float*)d_in[18];
    const float* n1b     = (const float*)d_in[19];
    const float* lin1_w  = (const float*)d_in[20];
    const float* lin1_b  = (const float*)d_in[21];
    const float* lin2_w  = (const float*)d_in[22];
    const float* lin2_b  = (const float*)d_in[23];
    const float* n3g     = (const float*)d_in[24];
    const float* n3b     = (const float*)d_in[25];

    static float *p_qk, *p_v, *p_att, *p_att2, *p_t1, *p_val, *p_off,
                 *p_attw, *p_samp, *p_ms, *p_t2, *p_f1, *p_f2;
    static bool init = false;
    if (!init) {
        void* p;
        cudaGetSymbolAddress(&p, g_qk);   p_qk   = (float*)p;
        cudaGetSymbolAddress(&p, g_v);    p_v    = (float*)p;
        cudaGetSymbolAddress(&p, g_att);  p_att  = (float*)p;
        cudaGetSymbolAddress(&p, g_att2); p_att2 = (float*)p;
        cudaGetSymbolAddress(&p, g_t1);   p_t1   = (float*)p;
        cudaGetSymbolAddress(&p, g_value);p_val  = (float*)p;
        cudaGetSymbolAddress(&p, g_off);  p_off  = (float*)p;
        cudaGetSymbolAddress(&p, g_attw); p_attw = (float*)p;
        cudaGetSymbolAddress(&p, g_samp); p_samp = (float*)p;
        cudaGetSymbolAddress(&p, g_ms);   p_ms   = (float*)p;
        cudaGetSymbolAddress(&p, g_t2);   p_t2   = (float*)p;
        cudaGetSymbolAddress(&p, g_ffn1); p_f1   = (float*)p;
        cudaGetSymbolAddress(&p, g_ffn2); p_f2   = (float*)p;
        init = true;
    }

    const dim3 blk(256);

    // 1) q|k = (tgt+qp) @ in_proj_w[0:512]^T
    gemm_tc<<<dim3(512/128, NTOK/128), blk>>>(tgt, qp, in_w, in_b, p_qk, NTOK, 256, 512, 0);
    // 2) v = tgt @ in_proj_w[512:768]^T
    gemm_tc<<<dim3(256/128, NTOK/128), blk>>>(tgt, nullptr, in_w + (size_t)512*256, in_b + 512, p_v, NTOK, 256, 256, 0);
    // 3) attention
    attn_kernel<<<dim3(LQ/128, BB*HH), dim3(128)>>>(p_qk, p_v, p_att);
    // 4) out_proj
    gemm_tc<<<dim3(256/128, NTOK/128), blk>>>(p_att, nullptr, out_w, out_b, p_att2, NTOK, 256, 256, 0);
    // 5) t1 = LN(tgt + att2)  [norm2]
    ln_kernel<<<NTOK/8, blk>>>(tgt, p_att2, n2g, n2b, p_t1);
    // 6) value = src @ value_w^T
    gemm_tc<<<dim3(256/128, NV/128), blk>>>(src, nullptr, value_w, value_b, p_val, NV, 256, 256, 0);
    // 7) off = (t1+qp) @ off_w^T
    gemm_tc<<<dim3(256/128, NTOK/128), blk>>>(p_t1, qp, off_w, off_b, p_off, NTOK, 256, 256, 0);
    // 8) attw = (t1+qp) @ attw_w^T
    gemm_tc<<<dim3(128/128, NTOK/128), blk>>>(p_t1, qp, attw_w, attw_b, p_attw, NTOK, 256, 128, 0);
    // 9) softmax over L*P per (token,h)
    softmax16_kernel<<<(NTOK*HH + 255)/256, blk>>>(p_attw);
    // 10) bilinear sampling
    sample_kernel<<<(NTOK*HH)/8, blk>>>(refpts, p_off, p_attw, p_val, p_samp);
    // 11) output projection of deformable attn
    gemm_tc<<<dim3(256/128, NTOK/128), blk>>>(p_samp, nullptr, outp_w, outp_b, p_ms, NTOK, 256, 256, 0);
    // 12) t2 = LN(t1 + ms)  [norm1]
    ln_kernel<<<NTOK/8, blk>>>(p_t1, p_ms, n1g, n1b, p_t2);
    // 13) ffn1 = relu(t2 @ lin1^T)
    gemm_tc<<<dim3(1024/128, NTOK/128), blk>>>(p_t2, nullptr, lin1_w, lin1_b, p_f1, NTOK, 256, 1024, 1);
    // 14) ffn2 = ffn1 @ lin2^T
    gemm_tc<<<dim3(256/128, NTOK/128), blk>>>(p_f1, nullptr, lin2_w, lin2_b, p_f2, NTOK, 1024, 256, 0);
    // 15) out = LN(t2 + ffn2)  [norm3]
    ln_kernel<<<NTOK/8, blk>>>(p_t2, p_f2, n3g, n3b, (float*)d_out);
}

// round 5
// speedup vs baseline: 1.8038x; 1.1543x over previous
#include <cuda_runtime.h>
#include <cuda_bf16.h>
#include <math.h>

// Problem constants
#define BB   16
#define LQ   1024
#define DD   256
#define HH   8
#define LL   4
#define PP   4
#define DFF  1024
#define LV   5440
#define DH   32
#define NTOK (BB*LQ)        // 16384
#define NV   (BB*LV)        // 87040

typedef unsigned long long ull;

__device__ __forceinline__ unsigned f2tf32(float f) {
    unsigned r;
    asm("cvt.rna.tf32.f32 %0, %1;" : "=r"(r) : "f"(f));
    return r;
}
__device__ __forceinline__ void mma_tf32(float* c, const unsigned* a, unsigned b0, unsigned b1) {
    asm volatile(
        "mma.sync.aligned.m16n8k8.row.col.f32.tf32.tf32.f32 "
        "{%0,%1,%2,%3}, {%4,%5,%6,%7}, {%8,%9}, {%0,%1,%2,%3};"
        : "+f"(c[0]), "+f"(c[1]), "+f"(c[2]), "+f"(c[3])
        : "r"(a[0]), "r"(a[1]), "r"(a[2]), "r"(a[3]), "r"(b0), "r"(b1));
}

// ---------------- scratch (device globals; no allocs allowed) ----------------
__device__ float g_qk  [(size_t)NTOK*512];
__device__ float g_v   [(size_t)NTOK*256];
__device__ float g_att [(size_t)NTOK*256];
__device__ float g_att2[(size_t)NTOK*256];
__device__ float g_t1  [(size_t)NTOK*256];
__device__ float g_value[(size_t)NV*256];
__device__ float g_off [(size_t)NTOK*256];
__device__ float g_attw[(size_t)NTOK*128];
__device__ float g_samp[(size_t)NTOK*256];
__device__ float g_ms  [(size_t)NTOK*256];
__device__ float g_t2  [(size_t)NTOK*256];
__device__ float g_ffn1[(size_t)NTOK*1024];
__device__ float g_ffn2[(size_t)NTOK*256];

// ---------------- tensor-core GEMM (tf32 mma.sync) ---------------------------
// C[N,M] = (A0 (+A1))[N,K] @ W[M,K]^T + bias  (optional relu)
// 128x128 tile, KC=32, 256 threads = 8 warps (2 row x 4 col), 64x32 per warp.
// smem rows pair-permuted: slot 2t holds k=t, slot 2t+1 holds k=t+4 within each
// 8-group -> every MMA fragment pair is one LDS.64, every fill store a STS.64.
#define GSTRIDE 36
__global__ void __launch_bounds__(256, 2) gemm_tc(
    const float* __restrict__ A0, const float* __restrict__ A1,
    const float* __restrict__ W,  const float* __restrict__ bias,
    float* __restrict__ C, int N, int K, int M, int relu)
{
    __shared__ unsigned As[128][GSTRIDE];
    __shared__ unsigned Bs[128][GSTRIDE];

    const int tid  = threadIdx.x;
    const int lane = tid & 31;
    const int wid  = tid >> 5;
    const int wr   = wid & 1;
    const int wc   = wid >> 1;
    const int g    = lane >> 2;
    const int tig  = lane & 3;
    const int r0 = blockIdx.y * 128;
    const int c0 = blockIdx.x * 128;

    float acc[4][4][4];
    #pragma unroll
    for (int mt = 0; mt < 4; mt++)
        #pragma unroll
        for (int nt = 0; nt < 4; nt++)
            #pragma unroll
            for (int c = 0; c < 4; c++) acc[mt][nt][c] = 0.f;

    // fill: warps 0-3 fill As (rows 0..127), warps 4-7 fill Bs
    const int frow = tid & 127;
    const int isB  = tid >> 7;
    const float* srcP  = isB ? (W + (size_t)(c0 + frow) * K)
                             : (A0 + (size_t)(r0 + frow) * K);
    const float* src1P = (!isB && A1) ? (A1 + (size_t)(r0 + frow) * K) : nullptr;
    unsigned (*S)[GSTRIDE] = isB ? Bs : As;

    for (int kt = 0; kt < K; kt += 32) {
        __syncthreads();
        #pragma unroll
        for (int grp = 0; grp < 4; grp++) {
            float4 lo = *(const float4*)(srcP + kt + grp * 8);
            float4 hi = *(const float4*)(srcP + kt + grp * 8 + 4);
            if (src1P) {
                float4 l1 = *(const float4*)(src1P + kt + grp * 8);
                float4 h1 = *(const float4*)(src1P + kt + grp * 8 + 4);
                lo.x += l1.x; lo.y += l1.y; lo.z += l1.z; lo.w += l1.w;
                hi.x += h1.x; hi.y += h1.y; hi.z += h1.z; hi.w += h1.w;
            }
            *(uint2*)&S[frow][grp*8+0] = make_uint2(f2tf32(lo.x), f2tf32(hi.x));
            *(uint2*)&S[frow][grp*8+2] = make_uint2(f2tf32(lo.y), f2tf32(hi.y));
            *(uint2*)&S[frow][grp*8+4] = make_uint2(f2tf32(lo.z), f2tf32(hi.z));
            *(uint2*)&S[frow][grp*8+6] = make_uint2(f2tf32(lo.w), f2tf32(hi.w));
        }
        __syncthreads();

        #pragma unroll
        for (int k8 = 0; k8 < 4; k8++) {
            unsigned af[4][4];
            #pragma unroll
            for (int mt = 0; mt < 4; mt++) {
                const int rowa = wr * 64 + mt * 16 + g;
                uint2 p0 = *(const uint2*)&As[rowa    ][k8 * 8 + 2 * tig];
                uint2 p1 = *(const uint2*)&As[rowa + 8][k8 * 8 + 2 * tig];
                af[mt][0] = p0.x; af[mt][1] = p1.x; af[mt][2] = p0.y; af[mt][3] = p1.y;
            }
            #pragma unroll
            for (int nt = 0; nt < 4; nt++) {
                const int coln = wc * 32 + nt * 8 + g;
                uint2 p = *(const uint2*)&Bs[coln][k8 * 8 + 2 * tig];
                #pragma unroll
                for (int mt = 0; mt < 4; mt++)
                    mma_tf32(acc[mt][nt], af[mt], p.x, p.y);
            }
        }
    }

    #pragma unroll
    for (int nt = 0; nt < 4; nt++) {
        const int col = c0 + wc * 32 + nt * 8 + 2 * tig;
        float2 bi = *(const float2*)(bias + col);
        #pragma unroll
        for (int mt = 0; mt < 4; mt++) {
            const int row = r0 + wr * 64 + mt * 16 + g;
            float2 lo, hi;
            lo.x = acc[mt][nt][0] + bi.x; lo.y = acc[mt][nt][1] + bi.y;
            hi.x = acc[mt][nt][2] + bi.x; hi.y = acc[mt][nt][3] + bi.y;
            if (relu) {
                lo.x = fmaxf(lo.x, 0.f); lo.y = fmaxf(lo.y, 0.f);
                hi.x = fmaxf(hi.x, 0.f); hi.y = fmaxf(hi.y, 0.f);
            }
            *(float2*)(C + (size_t)row * M + col)       = lo;
            *(float2*)(C + (size_t)(row + 8) * M + col) = hi;
        }
    }
}

// ---------------- tensor-core flash attention (tf32) -------------------------
// grid (LQ/64, B*H), 128 threads = 4 warps, 16 queries per warp.
// QK: [NTOK,512] (q | k), V: [NTOK,256] head-interleaved.
#define KSTR 36
#define VSTR 66
__global__ void __launch_bounds__(128) attn_tc(
    const float* __restrict__ QK, const float* __restrict__ V, float* __restrict__ O)
{
    __shared__ unsigned Ks[64][KSTR];
    __shared__ unsigned Vs[32][VSTR];

    const int bh = blockIdx.y;
    const int b = bh >> 3, h = bh & 7;
    const int q0 = blockIdx.x * 64;
    const int tid = threadIdx.x;
    const int lane = tid & 31;
    const int wid = tid >> 5;
    const int g = lane >> 2;
    const int tig = lane & 3;

    // Q fragments (scaled by 1/sqrt(DH), tf32)
    const float scale = 0.17677669529663687f;
    unsigned qf[4][4];
    {
        const size_t qb = ((size_t)b * LQ + q0 + wid * 16) * 512 + h * 32;
        #pragma unroll
        for (int s = 0; s < 4; s++) {
            qf[s][0] = f2tf32(QK[qb + (size_t)g      * 512 + s*8 + tig    ] * scale);
            qf[s][1] = f2tf32(QK[qb + (size_t)(g + 8)* 512 + s*8 + tig    ] * scale);
            qf[s][2] = f2tf32(QK[qb + (size_t)g      * 512 + s*8 + tig + 4] * scale);
            qf[s][3] = f2tf32(QK[qb + (size_t)(g + 8)* 512 + s*8 + tig + 4] * scale);
        }
    }

    float oa[4][4];
    #pragma unroll
    for (int i = 0; i < 4; i++)
        #pragma unroll
        for (int j = 0; j < 4; j++) oa[i][j] = 0.f;
    float m0 = -1e30f, m1 = -1e30f, l0 = 0.f, l1 = 0.f;

    const size_t kbase = ((size_t)b * LQ) * 512 + 256 + h * 32;
    const size_t vbase = ((size_t)b * LQ) * 256 + h * 32;

    for (int kt = 0; kt < LQ; kt += 64) {
        __syncthreads();
        // fill K tile [64 keys x 32 k], pair-permuted
        {
            const int key = tid >> 1, kh = (tid & 1) * 16;
            const float* kp = QK + kbase + (size_t)(kt + key) * 512 + kh;
            #pragma unroll
            for (int g2 = 0; g2 < 2; g2++) {
                float4 lo = *(const float4*)(kp + g2 * 8);
                float4 hi = *(const float4*)(kp + g2 * 8 + 4);
                const int d = kh + g2 * 8;
                *(uint2*)&Ks[key][d+0] = make_uint2(f2tf32(lo.x), f2tf32(hi.x));
                *(uint2*)&Ks[key][d+2] = make_uint2(f2tf32(lo.y), f2tf32(hi.y));
                *(uint2*)&Ks[key][d+4] = make_uint2(f2tf32(lo.z), f2tf32(hi.z));
                *(uint2*)&Ks[key][d+6] = make_uint2(f2tf32(lo.w), f2tf32(hi.w));
            }
        }
        // fill V tile transposed: Vs[d][perm(key)]
        {
            const int key = tid >> 1, dh = (tid & 1) * 16;
            const int j = key & 7;
            const int pos = (key >> 3) * 8 + 2 * (j & 3) + (j >> 2);
            const float* vp = V + vbase + (size_t)(kt + key) * 256 + dh;
            #pragma unroll
            for (int i = 0; i < 4; i++) {
                float4 v = *(const float4*)(vp + i * 4);
                Vs[dh + i*4 + 0][pos] = f2tf32(v.x);
                Vs[dh + i*4 + 1][pos] = f2tf32(v.y);
                Vs[dh + i*4 + 2][pos] = f2tf32(v.z);
                Vs[dh + i*4 + 3][pos] = f2tf32(v.w);
            }
        }
        __syncthreads();

        // S = Q K^T : 8 n-tiles x 4 k-steps
        float sa[8][4];
        #pragma unroll
        for (int nt = 0; nt < 8; nt++)
            #pragma unroll
            for (int c = 0; c < 4; c++) sa[nt][c] = 0.f;
        #pragma unroll
        for (int s = 0; s < 4; s++)
            #pragma unroll
            for (int nt = 0; nt < 8; nt++) {
                uint2 p = *(const uint2*)&Ks[nt*8 + g][s*8 + 2*tig];
                mma_tf32(sa[nt], qf[s], p.x, p.y);
            }

        // online softmax (thread rows: r0 = g, r1 = g+8 of warp tile)
        float cm0 = -1e30f, cm1 = -1e30f;
        #pragma unroll
        for (int nt = 0; nt < 8; nt++) {
            cm0 = fmaxf(cm0, fmaxf(sa[nt][0], sa[nt][1]));
            cm1 = fmaxf(cm1, fmaxf(sa[nt][2], sa[nt][3]));
        }
        cm0 = fmaxf(cm0, __shfl_xor_sync(0xffffffffu, cm0, 1));
        cm0 = fmaxf(cm0, __shfl_xor_sync(0xffffffffu, cm0, 2));
        cm1 = fmaxf(cm1, __shfl_xor_sync(0xffffffffu, cm1, 1));
        cm1 = fmaxf(cm1, __shfl_xor_sync(0xffffffffu, cm1, 2));
        const float nm0 = fmaxf(m0, cm0), nm1 = fmaxf(m1, cm1);
        const float r0s = __expf(m0 - nm0), r1s = __expf(m1 - nm1);
        l0 *= r0s; l1 *= r1s;
        #pragma unroll
        for (int d = 0; d < 4; d++) {
            oa[d][0] *= r0s; oa[d][1] *= r0s;
            oa[d][2] *= r1s; oa[d][3] *= r1s;
        }
        float ps0 = 0.f, ps1 = 0.f;
        #pragma unroll
        for (int nt = 0; nt < 8; nt++) {
            sa[nt][0] = __expf(sa[nt][0] - nm0); ps0 += sa[nt][0];
            sa[nt][1] = __expf(sa[nt][1] - nm0); ps0 += sa[nt][1];
            sa[nt][2] = __expf(sa[nt][2] - nm1); ps1 += sa[nt][2];
            sa[nt][3] = __expf(sa[nt][3] - nm1); ps1 += sa[nt][3];
        }
        ps0 += __shfl_xor_sync(0xffffffffu, ps0, 1);
        ps0 += __shfl_xor_sync(0xffffffffu, ps0, 2);
        ps1 += __shfl_xor_sync(0xffffffffu, ps1, 1);
        ps1 += __shfl_xor_sync(0xffffffffu, ps1, 2);
        l0 += ps0; l1 += ps1;
        m0 = nm0; m1 = nm1;

        // P (C-layout) -> A-layout via shfl, then O += P V
        const int src1 = (lane & ~3) | (tig >> 1);
        const int src2 = src1 + 2;
        #pragma unroll
        for (int nt = 0; nt < 8; nt++) {
            float v0a = __shfl_sync(0xffffffffu, sa[nt][0], src1);
            float v1a = __shfl_sync(0xffffffffu, sa[nt][1], src1);
            float v0b = __shfl_sync(0xffffffffu, sa[nt][0], src2);
            float v1b = __shfl_sync(0xffffffffu, sa[nt][1], src2);
            float w0a = __shfl_sync(0xffffffffu, sa[nt][2], src1);
            float w1a = __shfl_sync(0xffffffffu, sa[nt][3], src1);
            float w0b = __shfl_sync(0xffffffffu, sa[nt][2], src2);
            float w1b = __shfl_sync(0xffffffffu, sa[nt][3], src2);
            unsigned pa[4];
            pa[0] = f2tf32((tig & 1) ? v1a : v0a);   // P[g][nt*8+tig]
            pa[1] = f2tf32((tig & 1) ? w1a : w0a);   // P[g+8][nt*8+tig]
            pa[2] = f2tf32((tig & 1) ? v1b : v0b);   // P[g][nt*8+tig+4]
            pa[3] = f2tf32((tig & 1) ? w1b : w0b);   // P[g+8][nt*8+tig+4]
            #pragma unroll
            for (int d = 0; d < 4; d++) {
                uint2 bv = *(const uint2*)&Vs[d*8 + g][nt*8 + 2*tig];
                mma_tf32(oa[d], pa, bv.x, bv.y);
            }
        }
    }

    const float inv0 = 1.f / l0, inv1 = 1.f / l1;
    const size_t orow = ((size_t)b * LQ + q0 + wid * 16 + g) * 256 + h * 32;
    #pragma unroll
    for (int d = 0; d < 4; d++) {
        float2 lo, hi;
        lo.x = oa[d][0] * inv0; lo.y = oa[d][1] * inv0;
        hi.x = oa[d][2] * inv1; hi.y = oa[d][3] * inv1;
        *(float2*)(O + orow + d*8 + 2*tig)            = lo;
        *(float2*)(O + orow + 8*256 + d*8 + 2*tig)    = hi;
    }
}

// ---------------- residual + layernorm: Y = LN(A + Bres) ---------------------
__global__ void __launch_bounds__(256) ln_kernel(
    const float* __restrict__ A, const float* __restrict__ Bres,
    const float* __restrict__ g, const float* __restrict__ beta,
    float* __restrict__ Y)
{
    const int warp = threadIdx.x >> 5, lane = threadIdx.x & 31;
    const size_t row = (size_t)blockIdx.x * 8 + warp;
    const float* a = A    + row * 256;
    const float* b = Bres + row * 256;
    float v[8];
    #pragma unroll
    for (int i = 0; i < 2; i++) {
        float4 x = *(const float4*)(a + i*128 + lane*4);
        float4 y = *(const float4*)(b + i*128 + lane*4);
        v[i*4+0] = x.x + y.x; v[i*4+1] = x.y + y.y;
        v[i*4+2] = x.z + y.z; v[i*4+3] = x.w + y.w;
    }
    float sum = 0.f, sq = 0.f;
    #pragma unroll
    for (int i = 0; i < 8; i++) { sum += v[i]; sq = fmaf(v[i], v[i], sq); }
    #pragma unroll
    for (int off = 16; off > 0; off >>= 1) {
        sum += __shfl_xor_sync(0xffffffffu, sum, off);
        sq  += __shfl_xor_sync(0xffffffffu, sq,  off);
    }
    const float mean = sum * (1.f/256.f);
    const float var  = sq * (1.f/256.f) - mean * mean;
    const float inv  = rsqrtf(var + 1e-5f);
    #pragma unroll
    for (int i = 0; i < 2; i++) {
        const int col = i*128 + lane*4;
        float4 gg = *(const float4*)(g + col);
        float4 bb = *(const float4*)(beta + col);
        float4 out;
        out.x = (v[i*4+0]-mean)*inv*gg.x + bb.x;
        out.y = (v[i*4+1]-mean)*inv*gg.y + bb.y;
        out.z = (v[i*4+2]-mean)*inv*gg.z + bb.z;
        out.w = (v[i*4+3]-mean)*inv*gg.w + bb.w;
        *(float4*)(Y + row*256 + col) = out;
    }
}

// ---------------- softmax over 16 contiguous values per (token,h) ------------
__global__ void __launch_bounds__(256) softmax16_kernel(float* __restrict__ W)
{
    const int tid = blockIdx.x * 256 + threadIdx.x;
    if (tid >= NTOK * HH) return;
    float* p = W + (size_t)tid * 16;
    float v[16];
    #pragma unroll
    for (int i = 0; i < 4; i++) {
        float4 t = *(const float4*)(p + i*4);
        v[i*4+0]=t.x; v[i*4+1]=t.y; v[i*4+2]=t.z; v[i*4+3]=t.w;
    }
    float mx = v[0];
    #pragma unroll
    for (int i = 1; i < 16; i++) mx = fmaxf(mx, v[i]);
    float s = 0.f;
    #pragma unroll
    for (int i = 0; i < 16; i++) { v[i] = __expf(v[i]-mx); s += v[i]; }
    const float inv = 1.f / s;
    #pragma unroll
    for (int i = 0; i < 4; i++) {
        float4 t;
        t.x=v[i*4+0]*inv; t.y=v[i*4+1]*inv; t.z=v[i*4+2]*inv; t.w=v[i*4+3]*inv;
        *(float4*)(p + i*4) = t;
    }
}

// ---------------- deformable bilinear sampling -------------------------------
__device__ __forceinline__ float fetch_v(const float* __restrict__ value, size_t vb,
                                         int start, int WL2, int HL2, int xi, int yi)
{
    const bool ok = ((unsigned)xi < (unsigned)WL2) & ((unsigned)yi < (unsigned)HL2);
    const int xc = min(max(xi, 0), WL2 - 1);
    const int yc = min(max(yi, 0), HL2 - 1);
    const float val = value[vb + (size_t)(start + yc * WL2 + xc) * 256];
    return ok ? val : 0.f;
}

__global__ void __launch_bounds__(256) sample_kernel(
    const float* __restrict__ ref, const float* __restrict__ off,
    const float* __restrict__ attw, const float* __restrict__ value,
    float* __restrict__ out)
{
    const int wg   = blockIdx.x * 8 + (threadIdx.x >> 5);
    const int lane = threadIdx.x & 31;
    const int h  = wg & 7;
    const int tq = wg >> 3;            // b*LQ + q
    const int b  = tq >> 10;

    const float* refp = ref  + (size_t)tq * (LL*2);
    const float* offp = off  + (size_t)tq * 256 + h * 32;
    const float* awp  = attw + (size_t)tq * 128 + h * 16;
    const size_t vb   = ((size_t)b * LV) * 256 + h * 32 + lane;

    const int wls[4]    = {64, 32, 16, 8};
    const int hls[4]    = {64, 32, 16, 8};
    const int starts[4] = {0, 4096, 5120, 5376};

    float acc = 0.f;
    #pragma unroll
    for (int l = 0; l < 4; l++) {
        const int WL2 = wls[l], HL2 = hls[l], st = starts[l];
        const float rx = refp[l*2], ry = refp[l*2+1];
        #pragma unroll
        for (int p = 0; p < 4; p++) {
            const float ox = offp[(l*4+p)*2];
            const float oy = offp[(l*4+p)*2+1];
            const float aw = awp[l*4+p];
            const float x = fmaf(rx, (float)WL2, ox) - 0.5f;
            const float y = fmaf(ry, (float)HL2, oy) - 0.5f;
            const float xf = floorf(x), yf = floorf(y);
            const float lx = x - xf, ly = y - yf;
            const int x0 = (int)xf, y0 = (int)yf;
            const float v00 = fetch_v(value, vb, st, WL2, HL2, x0,   y0);
            const float v01 = fetch_v(value, vb, st, WL2, HL2, x0+1, y0);
            const float v10 = fetch_v(value, vb, st, WL2, HL2, x0,   y0+1);
            const float v11 = fetch_v(value, vb, st, WL2, HL2, x0+1, y0+1);
            const float top = v00 + lx * (v01 - v00);
            const float bot = v10 + lx * (v11 - v10);
            acc = fmaf(aw, top + ly * (bot - top), acc);
        }
    }
    out[(size_t)tq * 256 + h * 32 + lane] = acc;
}

// ---------------- host orchestration -----------------------------------------
extern "C" void kernel_launch(void* const* d_in, const int* in_sizes, int n_in,
                              void* d_out, int out_size)
{
    const float* tgt     = (const float*)d_in[0];
    const float* qp      = (const float*)d_in[1];
    const float* refpts  = (const float*)d_in[2];
    const float* src     = (const float*)d_in[3];
    const float* in_w    = (const float*)d_in[4];
    const float* in_b    = (const float*)d_in[5];
    const float* out_w   = (const float*)d_in[6];
    const float* out_b   = (const float*)d_in[7];
    const float* n2g     = (const float*)d_in[8];
    const float* n2b     = (const float*)d_in[9];
    const float* value_w = (const float*)d_in[10];
    const float* value_b = (const float*)d_in[11];
    const float* off_w   = (const float*)d_in[12];
    const float* off_b   = (const float*)d_in[13];
    const float* attw_w  = (const float*)d_in[14];
    const float* attw_b  = (const float*)d_in[15];
    const float* outp_w  = (const float*)d_in[16];
    const float* outp_b  = (const float*)d_in[17];
    const float* n1g     = (const float*)d_in[18];
    const float* n1b     = (const float*)d_in[19];
    const float* lin1_w  = (const float*)d_in[20];
    const float* lin1_b  = (const float*)d_in[21];
    const float* lin2_w  = (const float*)d_in[22];
    const float* lin2_b  = (const float*)d_in[23];
    const float* n3g     = (const float*)d_in[24];
    const float* n3b     = (const float*)d_in[25];

    static float *p_qk, *p_v, *p_att, *p_att2, *p_t1, *p_val, *p_off,
                 *p_attw, *p_samp, *p_ms, *p_t2, *p_f1, *p_f2;
    static bool init = false;
    if (!init) {
        void* p;
        cudaGetSymbolAddress(&p, g_qk);   p_qk   = (float*)p;
        cudaGetSymbolAddress(&p, g_v);    p_v    = (float*)p;
        cudaGetSymbolAddress(&p, g_att);  p_att  = (float*)p;
        cudaGetSymbolAddress(&p, g_att2); p_att2 = (float*)p;
        cudaGetSymbolAddress(&p, g_t1);   p_t1   = (float*)p;
        cudaGetSymbolAddress(&p, g_value);p_val  = (float*)p;
        cudaGetSymbolAddress(&p, g_off);  p_off  = (float*)p;
        cudaGetSymbolAddress(&p, g_attw); p_attw = (float*)p;
        cudaGetSymbolAddress(&p, g_samp); p_samp = (float*)p;
        cudaGetSymbolAddress(&p, g_ms);   p_ms   = (float*)p;
        cudaGetSymbolAddress(&p, g_t2);   p_t2   = (float*)p;
        cudaGetSymbolAddress(&p, g_ffn1); p_f1   = (float*)p;
        cudaGetSymbolAddress(&p, g_ffn2); p_f2   = (float*)p;
        init = true;
    }

    const dim3 blk(256);

    // 1) q|k = (tgt+qp) @ in_proj_w[0:512]^T
    gemm_tc<<<dim3(512/128, NTOK/128), blk>>>(tgt, qp, in_w, in_b, p_qk, NTOK, 256, 512, 0);
    // 2) v = tgt @ in_proj_w[512:768]^T
    gemm_tc<<<dim3(256/128, NTOK/128), blk>>>(tgt, nullptr, in_w + (size_t)512*256, in_b + 512, p_v, NTOK, 256, 256, 0);
    // 3) attention (tensor-core flash)
    attn_tc<<<dim3(LQ/64, BB*HH), dim3(128)>>>(p_qk, p_v, p_att);
    // 4) out_proj
    gemm_tc<<<dim3(256/128, NTOK/128), blk>>>(p_att, nullptr, out_w, out_b, p_att2, NTOK, 256, 256, 0);
    // 5) t1 = LN(tgt + att2)  [norm2]
    ln_kernel<<<NTOK/8, blk>>>(tgt, p_att2, n2g, n2b, p_t1);
    // 6) value = src @ value_w^T
    gemm_tc<<<dim3(256/128, NV/128), blk>>>(src, nullptr, value_w, value_b, p_val, NV, 256, 256, 0);
    // 7) off = (t1+qp) @ off_w^T
    gemm_tc<<<dim3(256/128, NTOK/128), blk>>>(p_t1, qp, off_w, off_b, p_off, NTOK, 256, 256, 0);
    // 8) attw = (t1+qp) @ attw_w^T
    gemm_tc<<<dim3(128/128, NTOK/128), blk>>>(p_t1, qp, attw_w, attw_b, p_attw, NTOK, 256, 128, 0);
    // 9) softmax over L*P per (token,h)
    softmax16_kernel<<<(NTOK*HH + 255)/256, blk>>>(p_attw);
    // 10) bilinear sampling
    sample_kernel<<<(NTOK*HH)/8, blk>>>(refpts, p_off, p_attw, p_val, p_samp);
    // 11) output projection of deformable attn
    gemm_tc<<<dim3(256/128, NTOK/128), blk>>>(p_samp, nullptr, outp_w, outp_b, p_ms, NTOK, 256, 256, 0);
    // 12) t2 = LN(t1 + ms)  [norm1]
    ln_kernel<<<NTOK/8, blk>>>(p_t1, p_ms, n1g, n1b, p_t2);
    // 13) ffn1 = relu(t2 @ lin1^T)
    gemm_tc<<<dim3(1024/128, NTOK/128), blk>>>(p_t2, nullptr, lin1_w, lin1_b, p_f1, NTOK, 256, 1024, 1);
    // 14) ffn2 = ffn1 @ lin2^T
    gemm_tc<<<dim3(256/128, NTOK/128), blk>>>(p_f1, nullptr, lin2_w, lin2_b, p_f2, NTOK, 1024, 256, 0);
    // 15) out = LN(t2 + ffn2)  [norm3]
    ln_kernel<<<NTOK/8, blk>>>(p_t2, p_f2, n3g, n3b, (float*)d_out);
}